// round 6
// baseline (speedup 1.0000x reference)
#include <cuda_runtime.h>
#include <cuda_bf16.h>
#include <math.h>
#include <stdint.h>

#define D_MODEL 512
#define BATCH   4
#define SEQ     4096
#define HW      128
#define ROWS    (BATCH * SEQ)    // 16384

// ---- scratch (static device arrays; no allocations allowed) ----
__device__ uint32_t g_xh[ROWS * 256];
__device__ uint32_t g_xl[ROWS * 256];
__device__ uint32_t g_wth[3 * 512 * 256];
__device__ uint32_t g_wtl[3 * 512 * 256];
__device__ uint32_t g_Qh[ROWS * 256];
__device__ uint32_t g_Ql[ROWS * 256];
__device__ uint32_t g_Kh[ROWS * 256];
__device__ uint32_t g_Kl[ROWS * 256];
__device__ uint32_t g_Vth[4 * 512 * 2048 + 256];
__device__ uint32_t g_Vtl[4 * 512 * 2048 + 256];

// ============================================================================
// helpers
// ============================================================================
__device__ __forceinline__ uint32_t smem_to_u32(const void* p) {
    uint32_t a;
    asm("{ .reg .u64 t; cvta.to.shared.u64 t, %1; cvt.u32.u64 %0, t; }" : "=r"(a) : "l"(p));
    return a;
}
__device__ __forceinline__ void cpa16(uint32_t dst, const void* src) {
    asm volatile("cp.async.cg.shared.global [%0], [%1], 16;" :: "r"(dst), "l"(src));
}
template <int N>
__device__ __forceinline__ void cpwait() {
    asm volatile("cp.async.wait_group %0;" :: "n"(N) : "memory");
}
__device__ __forceinline__ void cpcommit() {
    asm volatile("cp.async.commit_group;" ::: "memory");
}
__device__ __forceinline__ void ldm_x4(uint32_t* r, uint32_t addr) {
    asm volatile("ldmatrix.sync.aligned.m8n8.x4.shared.b16 {%0,%1,%2,%3}, [%4];"
                 : "=r"(r[0]), "=r"(r[1]), "=r"(r[2]), "=r"(r[3]) : "r"(addr));
}
__device__ __forceinline__ void mma_bf16(float* c, const uint32_t* a, const uint32_t* b) {
    asm volatile("mma.sync.aligned.m16n8k16.row.col.f32.bf16.bf16.f32 "
                 "{%0,%1,%2,%3}, {%4,%5,%6,%7}, {%8,%9}, {%0,%1,%2,%3};"
                 : "+f"(c[0]), "+f"(c[1]), "+f"(c[2]), "+f"(c[3])
                 : "r"(a[0]), "r"(a[1]), "r"(a[2]), "r"(a[3]), "r"(b[0]), "r"(b[1]));
}
__device__ __forceinline__ void pack_hl(float v0, float v1, uint32_t& hi, uint32_t& lo) {
    __nv_bfloat162 h2, l2;
    h2.x = __float2bfloat16_rn(v0); h2.y = __float2bfloat16_rn(v1);
    l2.x = __float2bfloat16_rn(v0 - __bfloat162float(h2.x));
    l2.y = __float2bfloat16_rn(v1 - __bfloat162float(h2.y));
    hi = *(uint32_t*)&h2; lo = *(uint32_t*)&l2;
}

// ============================================================================
// prep_x / prep_w
// ============================================================================
__global__ void __launch_bounds__(256) prep_x_kernel(const float* __restrict__ x)
{
    const int m = blockIdx.x, p = threadIdx.x;
    const float2 v = *(const float2*)&x[(size_t)m * D_MODEL + 2 * p];
    uint32_t hi, lo;
    pack_hl(v.x, v.y, hi, lo);
    g_xh[m * 256 + p] = hi;
    g_xl[m * 256 + p] = lo;
}

__global__ void __launch_bounds__(256) prep_w_kernel(
    const float* __restrict__ Wq, const float* __restrict__ Wk, const float* __restrict__ Wv)
{
    const int z = blockIdx.x >> 9, n = blockIdx.x & 511, p = threadIdx.x;
    const float* W = (z == 0) ? Wq : ((z == 1) ? Wk : Wv);
    const float w0 = W[(size_t)(2 * p) * D_MODEL + n];
    const float w1 = W[(size_t)(2 * p + 1) * D_MODEL + n];
    uint32_t hi, lo;
    pack_hl(w0, w1, hi, lo);
    const size_t o = (size_t)(z * 512 + n) * 256 + p;
    g_wth[o] = hi;
    g_wtl[o] = lo;
}

// ============================================================================
// proj_mma: 256x128 CTA tile, 512 threads (16 warps, 4m x 4n, 64x32 warp tile)
// 24 stages of K=64 bf16, cp.async double buffer. bf16 hi/lo epilogues.
// ============================================================================
#define P2_STRB 144
#define P2_ABUF (256 * P2_STRB)       // 36864
#define P2_BBUF (128 * P2_STRB)       // 18432
#define P2_PAIR (P2_ABUF + P2_BBUF)   // 55296
#define P2_SMEM (256 * 132 * 4)       // 135168 (>= 2*P2_PAIR, covers V staging)

__device__ __forceinline__ void proj_issue_stage(int s, uint32_t smem_base,
                                                 int m0, int n0, int z, int tid)
{
    const int part = s >> 3;
    const int k0w = (s & 7) * 32;
    const uint32_t* Asrc = (part < 2) ? g_xh : g_xl;
    const uint32_t* Bsrc = ((part == 1) ? g_wtl : g_wth) + (size_t)z * 512 * 256;
    const uint32_t abase = smem_base + (uint32_t)((s & 1) * P2_PAIR);
    const uint32_t bbase = abase + P2_ABUF;
    #pragma unroll
    for (int t = 0; t < 4; t++) {                  // A: 256 rows x 8 chunks
        const int idx = t * 512 + tid;
        const int row = idx >> 3, ch = idx & 7;
        cpa16(abase + row * P2_STRB + ch * 16, Asrc + (size_t)(m0 + row) * 256 + k0w + ch * 4);
    }
    #pragma unroll
    for (int t = 0; t < 2; t++) {                  // B: 128 rows x 8 chunks
        const int idx = t * 512 + tid;
        const int row = idx >> 3, ch = idx & 7;
        cpa16(bbase + row * P2_STRB + ch * 16, Bsrc + (size_t)(n0 + row) * 256 + k0w + ch * 4);
    }
    cpcommit();
}

__global__ void __launch_bounds__(512) proj_mma_kernel(
    const float* __restrict__ bq, const float* __restrict__ bk, const float* __restrict__ bv)
{
    extern __shared__ char smg[];
    const uint32_t smem_base = smem_to_u32(smg);
    const int tid = threadIdx.x;
    const int wid = tid >> 5, lane = tid & 31;
    const int nt = blockIdx.x, mt = blockIdx.y, z = blockIdx.z;
    const int m0 = mt * 256, n0 = nt * 128;
    const float* bias = (z == 0) ? bq : ((z == 1) ? bk : bv);

    const int wm = wid & 3;        // 4 m-warps (64 rows each)
    const int wn = wid >> 2;       // 4 n-warps (32 cols each)

    float c[4][4][4];
    #pragma unroll
    for (int i = 0; i < 4; i++)
        #pragma unroll
        for (int j = 0; j < 4; j++)
            #pragma unroll
            for (int q = 0; q < 4; q++) c[i][j][q] = 0.f;

    const int a_row = wm * 64 + (lane & 15);
    const int a_colh = (lane >> 4) * 8;
    const int b_row = wn * 32 + (lane >> 4) * 8 + (lane & 7);
    const int b_colh = ((lane >> 3) & 1) * 8;

    proj_issue_stage(0, smem_base, m0, n0, z, tid);

    for (int s = 0; s < 24; s++) {
        if (s + 1 < 24) {
            proj_issue_stage(s + 1, smem_base, m0, n0, z, tid);
            cpwait<1>();
        } else {
            cpwait<0>();
        }
        __syncthreads();

        const uint32_t abase = smem_base + (uint32_t)((s & 1) * P2_PAIR);
        const uint32_t bbase = abase + P2_ABUF;

        #pragma unroll
        for (int kk = 0; kk < 4; kk++) {
            const int k0 = kk * 16;
            uint32_t af[4][4], bf[2][4];
            #pragma unroll
            for (int i = 0; i < 4; i++)
                ldm_x4(af[i], abase + (uint32_t)((a_row + i * 16) * P2_STRB + (k0 + a_colh) * 2));
            #pragma unroll
            for (int j = 0; j < 2; j++)
                ldm_x4(bf[j], bbase + (uint32_t)((b_row + j * 16) * P2_STRB + (k0 + b_colh) * 2));
            #pragma unroll
            for (int i = 0; i < 4; i++)
                #pragma unroll
                for (int j = 0; j < 4; j++)
                    mma_bf16(c[i][j], af[i], &bf[j >> 1][(j & 1) * 2]);
        }
        __syncthreads();
    }

    if (z < 2) {
        uint32_t* oh = (z == 0) ? g_Qh : g_Kh;
        uint32_t* ol = (z == 0) ? g_Ql : g_Kl;
        #pragma unroll
        for (int i = 0; i < 4; i++) {
            const int gm = m0 + wm * 64 + i * 16 + (lane >> 2);
            #pragma unroll
            for (int j = 0; j < 4; j++) {
                const int gn = n0 + wn * 32 + j * 8 + (lane & 3) * 2;
                const float b0 = bias[gn], b1 = bias[gn + 1];
                uint32_t hi, lo;
                pack_hl(c[i][j][0] + b0, c[i][j][1] + b1, hi, lo);
                oh[(size_t)gm * 256 + gn / 2] = hi;
                ol[(size_t)gm * 256 + gn / 2] = lo;
                pack_hl(c[i][j][2] + b0, c[i][j][3] + b1, hi, lo);
                oh[(size_t)(gm + 8) * 256 + gn / 2] = hi;
                ol[(size_t)(gm + 8) * 256 + gn / 2] = lo;
            }
        }
    } else {
        // V: stage fp32 into smem [256][132], then pack transposed to [d][s]
        float* st = (float*)smg;
        #pragma unroll
        for (int i = 0; i < 4; i++) {
            const int r0 = wm * 64 + i * 16 + (lane >> 2);
            #pragma unroll
            for (int j = 0; j < 4; j++) {
                const int col = wn * 32 + j * 8 + (lane & 3) * 2;
                const float b0 = bias[n0 + col], b1 = bias[n0 + col + 1];
                st[r0 * 132 + col]           = c[i][j][0] + b0;
                st[r0 * 132 + col + 1]       = c[i][j][1] + b1;
                st[(r0 + 8) * 132 + col]     = c[i][j][2] + b0;
                st[(r0 + 8) * 132 + col + 1] = c[i][j][3] + b1;
            }
        }
        __syncthreads();
        const int bb2 = m0 >> 12;
        const int s0 = m0 & 4095;
        const int n = tid & 127, h = tid >> 7;          // h: 0..3 -> 64 rows each
        const size_t obase = ((size_t)bb2 * 512 + n0 + n) * 2048 + (size_t)((s0 + h * 64) / 2);
        #pragma unroll
        for (int w = 0; w < 32; w++) {
            const int m = h * 64 + 2 * w;
            uint32_t hi, lo;
            pack_hl(st[m * 132 + n], st[(m + 1) * 132 + n], hi, lo);
            g_Vth[obase + w] = hi;
            g_Vtl[obase + w] = lo;
        }
    }
}

// ============================================================================
// attn_mma: unchanged from R5 (validated, 151us)
// ============================================================================
#define NKEY   320
#define A1BUF  9216
#define B1BUF  46080
#define PAIR1  (A1BUF + B1BUF)
#define R1SZ   (2 * PAIR1)
#define PH_OFF R1SZ
#define PL_OFF (R1SZ + 41984)
#define ATT_SMEM (R1SZ + 2 * 41984)
#define PSTRW  164
#define B2BUF  36864
#define SSTR   321

__device__ __forceinline__ void attn_issue1(int s, uint32_t sb, int b, int q0,
                                            int jlo, int tid)
{
    const int part = s >> 3, dc = s & 7;
    const uint32_t* Asrc = ((part < 2) ? g_Qh : g_Ql) + (size_t)(b * SEQ + q0) * 256 + dc * 32;
    const uint32_t* Bsrc = ((part == 1) ? g_Kl : g_Kh) + (size_t)b * SEQ * 256 + dc * 32;
    const uint32_t ab = sb + (uint32_t)((s & 1) * PAIR1);
    const uint32_t bb = ab + A1BUF;
    #pragma unroll
    for (int t = 0; t < 2; t++) {
        const int idx = t * 256 + tid;
        const int row = idx >> 3, ch = idx & 7;
        cpa16(ab + row * 144 + ch * 16, Asrc + (size_t)row * 256 + ch * 4);
    }
    #pragma unroll
    for (int t = 0; t < 10; t++) {
        const int idx = t * 256 + tid;
        const int row = idx >> 3, ch = idx & 7;
        int jr = jlo + row; if (jr > SEQ - 1) jr = SEQ - 1;
        cpa16(bb + row * 144 + ch * 16, Bsrc + (size_t)jr * 256 + ch * 4);
    }
    cpcommit();
}

__device__ __forceinline__ void attn_issue2(int s, int nh, uint32_t sb, int b,
                                            int jlo, int tid)
{
    const int q = s / 5, kc = s % 5;
    const uint32_t* Bsrc = (q == 1) ? g_Vtl : g_Vth;
    const size_t base = (size_t)b * 512 * 2048 + (size_t)(jlo / 2 + kc * 32);
    const uint32_t bb = sb + (uint32_t)((s & 1) * B2BUF);
    #pragma unroll
    for (int t = 0; t < 8; t++) {
        const int idx = t * 256 + tid;
        const int row = idx >> 3, ch = idx & 7;
        cpa16(bb + row * 144 + ch * 16, Bsrc + base + (size_t)(nh * 256 + row) * 2048 + ch * 4);
    }
    cpcommit();
}

__global__ void __launch_bounds__(256) attn_mma_kernel(float* __restrict__ outp)
{
    extern __shared__ char smc[];
    const uint32_t sb = smem_to_u32(smc);
    float* S = (float*)smc;
    const int tid = threadIdx.x, wid = tid >> 5, lane = tid & 31;
    const int q0 = blockIdx.x * 64, b = blockIdx.y;
    const int jlo = (q0 - HW > 0) ? q0 - HW : 0;
    const int jhi = (q0 + 63 + HW < SEQ - 1) ? q0 + 63 + HW : SEQ - 1;
    const int nk = jhi - jlo + 1;
    const int wm = wid & 1, wn = wid >> 1;

    float c1[2][10][4];
    #pragma unroll
    for (int i = 0; i < 2; i++)
        #pragma unroll
        for (int j = 0; j < 10; j++)
            #pragma unroll
            for (int q = 0; q < 4; q++) c1[i][j][q] = 0.f;

    attn_issue1(0, sb, b, q0, jlo, tid);

    for (int s = 0; s < 24; s++) {
        if (s + 1 < 24) { attn_issue1(s + 1, sb, b, q0, jlo, tid); cpwait<1>(); }
        else            { cpwait<0>(); }
        __syncthreads();
        const uint32_t ab = sb + (uint32_t)((s & 1) * PAIR1);
        const uint32_t bb = ab + A1BUF;
        #pragma unroll
        for (int kk = 0; kk < 4; kk++) {
            uint32_t af[2][4], bf[5][4];
            #pragma unroll
            for (int i = 0; i < 2; i++)
                ldm_x4(af[i], ab + (uint32_t)((wm * 32 + i * 16 + (lane & 15)) * 144
                                              + (kk * 16 + (lane >> 4) * 8) * 2));
            #pragma unroll
            for (int jj = 0; jj < 5; jj++)
                ldm_x4(bf[jj], bb + (uint32_t)((wn * 80 + jj * 16 + (lane >> 4) * 8 + (lane & 7)) * 144
                                               + (kk * 16 + ((lane >> 3) & 1) * 8) * 2));
            #pragma unroll
            for (int i = 0; i < 2; i++)
                #pragma unroll
                for (int j = 0; j < 10; j++)
                    mma_bf16(c1[i][j], af[i], &bf[j >> 1][(j & 1) * 2]);
        }
        __syncthreads();
    }

    const float scale = 0.044194173824159216f;
    #pragma unroll
    for (int i = 0; i < 2; i++) {
        const int r = wm * 32 + i * 16 + (lane >> 2);
        #pragma unroll
        for (int j = 0; j < 10; j++) {
            const int n = wn * 80 + j * 8 + (lane & 3) * 2;
            #pragma unroll
            for (int reg = 0; reg < 4; reg++) {
                const int rr = r + ((reg >= 2) ? 8 : 0);
                const int nn = n + (reg & 1);
                const int d = (q0 + rr) - (jlo + nn);
                const bool valid = (nn < nk) && (d <= HW) && (d >= -HW);
                S[rr * SSTR + nn] = valid ? c1[i][j][reg] * scale : -INFINITY;
            }
        }
    }
    __syncthreads();

    {
        const int m = tid >> 2, sub = tid & 3;
        float mx = -INFINITY;
        for (int n = sub; n < NKEY; n += 4) mx = fmaxf(mx, S[m * SSTR + n]);
        mx = fmaxf(mx, __shfl_xor_sync(0xffffffffu, mx, 1));
        mx = fmaxf(mx, __shfl_xor_sync(0xffffffffu, mx, 2));
        float sum = 0.f;
        for (int n = sub; n < NKEY; n += 4) {
            const float e = __expf(S[m * SSTR + n] - mx);
            S[m * SSTR + n] = e;
            sum += e;
        }
        sum += __shfl_xor_sync(0xffffffffu, sum, 1);
        sum += __shfl_xor_sync(0xffffffffu, sum, 2);
        const float inv = 1.f / sum;
        __syncwarp();
        uint32_t* Ph = (uint32_t*)(smc + PH_OFF);
        uint32_t* Pl = (uint32_t*)(smc + PL_OFF);
        for (int w = sub; w < 160; w += 4) {
            const float p0 = S[m * SSTR + 2 * w] * inv;
            const float p1 = S[m * SSTR + 2 * w + 1] * inv;
            uint32_t hi, lo;
            pack_hl(p0, p1, hi, lo);
            Ph[m * PSTRW + w] = hi;
            Pl[m * PSTRW + w] = lo;
        }
    }
    __syncthreads();

    float* O = outp + ((size_t)b * SEQ + q0) * D_MODEL;
    for (int nh = 0; nh < 2; nh++) {
        float c2[2][8][4];
        #pragma unroll
        for (int i = 0; i < 2; i++)
            #pragma unroll
            for (int j = 0; j < 8; j++)
                #pragma unroll
                for (int q = 0; q < 4; q++) c2[i][j][q] = 0.f;

        attn_issue2(0, nh, sb, b, jlo, tid);
        for (int s = 0; s < 15; s++) {
            if (s + 1 < 15) { attn_issue2(s + 1, nh, sb, b, jlo, tid); cpwait<1>(); }
            else            { cpwait<0>(); }
            __syncthreads();
            const uint32_t bb = sb + (uint32_t)((s & 1) * B2BUF);
            const int kc = s % 5;
            const uint32_t pbase = sb + (uint32_t)(((s / 5) < 2) ? PH_OFF : PL_OFF);
            #pragma unroll
            for (int kk = 0; kk < 4; kk++) {
                uint32_t af[2][4], bf[4][4];
                #pragma unroll
                for (int i = 0; i < 2; i++)
                    ldm_x4(af[i], pbase + (uint32_t)((wm * 32 + i * 16 + (lane & 15)) * (PSTRW * 4)
                                   + (kc * 64 + kk * 16 + (lane >> 4) * 8) * 2));
                #pragma unroll
                for (int jj = 0; jj < 4; jj++)
                    ldm_x4(bf[jj], bb + (uint32_t)((wn * 64 + jj * 16 + (lane >> 4) * 8 + (lane & 7)) * 144
                                   + (kk * 16 + ((lane >> 3) & 1) * 8) * 2));
                #pragma unroll
                for (int i = 0; i < 2; i++)
                    #pragma unroll
                    for (int j = 0; j < 8; j++)
                        mma_bf16(c2[i][j], af[i], &bf[j >> 1][(j & 1) * 2]);
            }
            __syncthreads();
        }

        #pragma unroll
        for (int i = 0; i < 2; i++) {
            const int r = wm * 32 + i * 16 + (lane >> 2);
            #pragma unroll
            for (int j = 0; j < 8; j++) {
                const int dcol = nh * 256 + wn * 64 + j * 8 + (lane & 3) * 2;
                float2 v0 = { c2[i][j][0], c2[i][j][1] };
                float2 v1 = { c2[i][j][2], c2[i][j][3] };
                *(float2*)&O[(size_t)r * D_MODEL + dcol] = v0;
                *(float2*)&O[(size_t)(r + 8) * D_MODEL + dcol] = v1;
            }
        }
    }
}

// ============================================================================
extern "C" void kernel_launch(void* const* d_in, const int* in_sizes, int n_in,
                              void* d_out, int out_size)
{
    const float* x  = (const float*)d_in[0];
    const float* Wq = (const float*)d_in[1];
    const float* bq = (const float*)d_in[2];
    const float* Wk = (const float*)d_in[3];
    const float* bk = (const float*)d_in[4];
    const float* Wv = (const float*)d_in[5];
    const float* bv = (const float*)d_in[6];
    float* out = (float*)d_out;

    static int attr_set = 0;
    if (!attr_set) {
        cudaFuncSetAttribute(proj_mma_kernel, cudaFuncAttributeMaxDynamicSharedMemorySize,
                             P2_SMEM);
        cudaFuncSetAttribute(attn_mma_kernel, cudaFuncAttributeMaxDynamicSharedMemorySize,
                             ATT_SMEM);
        attr_set = 1;
    }

    prep_x_kernel<<<ROWS, 256>>>(x);
    prep_w_kernel<<<3 * 512, 256>>>(Wq, Wk, Wv);
    proj_mma_kernel<<<dim3(D_MODEL / 128, ROWS / 256, 3), 512, P2_SMEM>>>(bq, bk, bv);
    attn_mma_kernel<<<dim3(SEQ / 64, BATCH), 256, ATT_SMEM>>>(out);
}